// round 2
// baseline (speedup 1.0000x reference)
#include <cuda_runtime.h>
#include <math_constants.h>

// MultiSimilarityLoss: sim_mat [8192,8192] f32, labels [8192] i64-or-i32 -> scalar f32
//
// One CTA per row, 512 threads, 16 elems/thread in registers.
// Pass 1: min over positives / max over negatives (block reduce).
// Pass 2 (registers only): masked exp sums; exp>0 so "any selected" == sum>0.
// Row losses -> __device__ array -> deterministic single-block reduce.
//
// Labels dtype is detected on-device: if every odd 32-bit word of the first
// 4096 label slots is zero, the buffer is int64 (values < 1024 => high words
// zero); otherwise it is int32. Deterministic: same input -> same detection.

constexpr int BN        = 8192;
constexpr int NTHREADS  = 512;
constexpr int PER       = BN / NTHREADS;   // 16
constexpr int NWARPS    = NTHREADS / 32;   // 16
constexpr float F_EPS       = 1e-5f;
constexpr float F_MARGIN    = 0.1f;
constexpr float F_THRESH    = 0.5f;
constexpr float F_SCALE_POS = 2.0f;
constexpr float F_SCALE_NEG = 40.0f;

__device__ int   g_labels[BN];
__device__ float g_row_loss[BN];

// Single block: detect dtype, then convert all labels to int32 in g_labels.
__global__ __launch_bounds__(1024) void prep_labels_kernel(const void* __restrict__ labels_raw) {
    const int tid = threadIdx.x;
    const unsigned* w = (const unsigned*)labels_raw;

    // OR the odd 32-bit words of the first 4096 label slots.
    // int64 layout: those are high words, all zero (labels < 1024).
    // int32 layout: those are labels[1,3,...,8191's first half], ~0 prob all zero.
    // Reads stay within 32 KB, in-bounds for either buffer size.
    unsigned f = 0;
    for (int i = tid; i < BN / 2; i += 1024) f |= w[2 * i + 1];
    #pragma unroll
    for (int o = 16; o; o >>= 1) f |= __shfl_xor_sync(0xffffffffu, f, o);

    __shared__ unsigned s_or[32];
    if ((tid & 31) == 0) s_or[tid >> 5] = f;
    __syncthreads();
    __shared__ int s_is64;
    if (tid == 0) {
        unsigned t = 0;
        #pragma unroll
        for (int i = 0; i < 32; i++) t |= s_or[i];
        s_is64 = (t == 0u) ? 1 : 0;
    }
    __syncthreads();

    if (s_is64) {
        const long long* l64 = (const long long*)labels_raw;
        for (int i = tid; i < BN; i += 1024) g_labels[i] = (int)l64[i];
    } else {
        const int* l32 = (const int*)labels_raw;
        for (int i = tid; i < BN; i += 1024) g_labels[i] = l32[i];
    }
}

__global__ __launch_bounds__(NTHREADS) void row_kernel(const float* __restrict__ sim) {
    const int row  = blockIdx.x;
    const int tid  = threadIdx.x;
    const int lane = tid & 31;
    const int warp = tid >> 5;
    const int my_label = g_labels[row];

    const float4* __restrict__ srow4 = reinterpret_cast<const float4*>(sim + (size_t)row * BN);
    const int4*   __restrict__ lab4  = reinterpret_cast<const int4*>(g_labels);

    float v[PER];
    unsigned pos_bits = 0u, neg_bits = 0u;
    float mn = CUDART_INF_F;    // min over positives
    float mx = -CUDART_INF_F;   // max over negatives

    #pragma unroll
    for (int k = 0; k < PER / 4; k++) {
        int j4 = tid + k * NTHREADS;           // coalesced float4 index
        float4 s4 = srow4[j4];
        int4   l4 = lab4[j4];
        float sv[4] = {s4.x, s4.y, s4.z, s4.w};
        int   lv[4] = {l4.x, l4.y, l4.z, l4.w};
        #pragma unroll
        for (int e = 0; e < 4; e++) {
            int idx = k * 4 + e;
            float s = sv[e];
            v[idx] = s;
            bool same = (lv[e] == my_label);
            bool pos  = same && (s < 1.0f - F_EPS);
            bool neg  = !same;
            if (pos) { pos_bits |= (1u << idx); mn = fminf(mn, s); }
            if (neg) { neg_bits |= (1u << idx); mx = fmaxf(mx, s); }
        }
    }

    // ---- block reduce min_pos / max_neg ----
    __shared__ float s_mn[NWARPS], s_mx[NWARPS];
    __shared__ float s_minpos, s_maxneg;
    #pragma unroll
    for (int o = 16; o; o >>= 1) {
        mn = fminf(mn, __shfl_xor_sync(0xffffffffu, mn, o));
        mx = fmaxf(mx, __shfl_xor_sync(0xffffffffu, mx, o));
    }
    if (lane == 0) { s_mn[warp] = mn; s_mx[warp] = mx; }
    __syncthreads();
    if (warp == 0) {
        float a = (lane < NWARPS) ? s_mn[lane] : CUDART_INF_F;
        float b = (lane < NWARPS) ? s_mx[lane] : -CUDART_INF_F;
        #pragma unroll
        for (int o = 8; o; o >>= 1) {
            a = fminf(a, __shfl_xor_sync(0xffffffffu, a, o));
            b = fmaxf(b, __shfl_xor_sync(0xffffffffu, b, o));
        }
        if (lane == 0) { s_minpos = a; s_maxneg = b; }
    }
    __syncthreads();
    const float min_pos = s_minpos;
    const float max_neg = s_maxneg;

    // ---- pass 2 from registers: masked exp sums ----
    float pos_sum = 0.0f, neg_sum = 0.0f;
    #pragma unroll
    for (int idx = 0; idx < PER; idx++) {
        float s = v[idx];
        bool selp = ((pos_bits >> idx) & 1u) && (s - F_MARGIN < max_neg);
        bool seln = ((neg_bits >> idx) & 1u) && (s + F_MARGIN > min_pos);
        if (selp) pos_sum += __expf(-F_SCALE_POS * (s - F_THRESH));
        if (seln) neg_sum += __expf( F_SCALE_NEG * (s - F_THRESH));
    }
    #pragma unroll
    for (int o = 16; o; o >>= 1) {
        pos_sum += __shfl_xor_sync(0xffffffffu, pos_sum, o);
        neg_sum += __shfl_xor_sync(0xffffffffu, neg_sum, o);
    }
    __shared__ float s_ps[NWARPS], s_ns[NWARPS];
    if (lane == 0) { s_ps[warp] = pos_sum; s_ns[warp] = neg_sum; }
    __syncthreads();
    if (tid == 0) {
        float ps = 0.0f, ns = 0.0f;
        #pragma unroll
        for (int w = 0; w < NWARPS; w++) { ps += s_ps[w]; ns += s_ns[w]; }
        // exp(x) > 0 always, so ps>0 <=> any(sel_pos), ns>0 <=> any(sel_neg)
        float loss = 0.0f;
        if (ps > 0.0f && ns > 0.0f)
            loss = log1pf(ps) / F_SCALE_POS + log1pf(ns) / F_SCALE_NEG;
        g_row_loss[row] = loss;
    }
}

__global__ __launch_bounds__(1024) void reduce_kernel(float* __restrict__ out) {
    int tid = threadIdx.x;
    float sum = 0.0f;
    #pragma unroll
    for (int i = 0; i < BN / 1024; i++) sum += g_row_loss[tid + i * 1024];
    __shared__ float s[32];
    #pragma unroll
    for (int o = 16; o; o >>= 1) sum += __shfl_xor_sync(0xffffffffu, sum, o);
    if ((tid & 31) == 0) s[tid >> 5] = sum;
    __syncthreads();
    if (tid < 32) {
        float x = s[tid];
        #pragma unroll
        for (int o = 16; o; o >>= 1) x += __shfl_xor_sync(0xffffffffu, x, o);
        if (tid == 0) out[0] = x / (float)BN;
    }
}

extern "C" void kernel_launch(void* const* d_in, const int* in_sizes, int n_in,
                              void* d_out, int out_size) {
    // Guard against input ordering: sim has BN*BN elements, labels BN.
    const void* p0 = d_in[0];
    const void* p1 = d_in[1];
    const float* sim;
    const void*  labels;
    if (in_sizes[0] == BN) { labels = p0; sim = (const float*)p1; }
    else                   { sim = (const float*)p0; labels = p1; }
    float* out = (float*)d_out;

    prep_labels_kernel<<<1, 1024>>>(labels);
    row_kernel<<<BN, NTHREADS>>>(sim);
    reduce_kernel<<<1, 1024>>>(out);
}

// round 3
// speedup vs baseline: 1.6656x; 1.6656x over previous
#include <cuda_runtime.h>
#include <math_constants.h>

// MultiSimilarityLoss: sim_mat [8192,8192] f32, labels [8192] i64-or-i32 -> scalar f32
//
// Issue-slot-optimized rewrite:
//  - Poison encoding: same-labeled elements stored as x = s - 4 (in [-5,-3]).
//    * max over negatives = unpredicated fmax over x (poison can't win).
//    * neg selection in pass 2 = single compare x > tn (poison auto-fails).
//    * positives recoverable in a rare branch via x < ~-3.00001.
//  - Dense pass 2 per element: FSETP + FFMA + MUFU.EX2 + predicated FADD (4 slots).
//  - Pos-side exp lives in a branch taken by ~39% of warps (positives ~8/row).

constexpr int BN        = 8192;
constexpr int NTHREADS  = 512;
constexpr int PER       = BN / NTHREADS;   // 16
constexpr int NWARPS    = NTHREADS / 32;   // 16

constexpr float ONE_MEPS = 1.0f - 1e-5f;          // pos threshold on s
constexpr float POISON   = 4.0f;
constexpr float PB       = ONE_MEPS - POISON;     // poisoned pos boundary ~ -3.00001
// exp(40(s-0.5)) = exp2(s*K40 + C40)
constexpr float K40 = 57.706801635558536f;        //  40*log2(e)
constexpr float C40 = -28.853400817779268f;       // -20*log2(e)
// exp(-2(s-0.5)) with s = x+4  ->  exp2(x*KP + CP)
constexpr float KP  = -2.885390081777927f;        //  -2*log2(e)
constexpr float CP  = -10.098865286222744f;       //  -7*log2(e)

__device__ int   g_labels[BN];
__device__ float g_row_loss[BN];

__device__ __forceinline__ float ex2(float a) {
    float r;
    asm("ex2.approx.ftz.f32 %0, %1;" : "=f"(r) : "f"(a));
    return r;
}

// 16 blocks x 512: per-block redundant dtype detection (odd 32-bit words of the
// first 4096 label slots are all zero iff int64 with values < 1024), then each
// block converts a grid-strided slice. Deterministic.
__global__ __launch_bounds__(512) void prep_labels_kernel(const void* __restrict__ labels_raw) {
    const int tid = threadIdx.x;
    const unsigned* w = (const unsigned*)labels_raw;

    unsigned f = 0;
    for (int i = tid; i < BN / 2; i += 512) f |= w[2 * i + 1];
    #pragma unroll
    for (int o = 16; o; o >>= 1) f |= __shfl_xor_sync(0xffffffffu, f, o);

    __shared__ unsigned s_or[16];
    __shared__ int s_is64;
    if ((tid & 31) == 0) s_or[tid >> 5] = f;
    __syncthreads();
    if (tid == 0) {
        unsigned t = 0;
        #pragma unroll
        for (int i = 0; i < 16; i++) t |= s_or[i];
        s_is64 = (t == 0u) ? 1 : 0;
    }
    __syncthreads();

    int start = blockIdx.x * 512 + tid;
    if (s_is64) {
        const long long* l64 = (const long long*)labels_raw;
        for (int i = start; i < BN; i += 512 * 16) g_labels[i] = (int)l64[i];
    } else {
        const int* l32 = (const int*)labels_raw;
        for (int i = start; i < BN; i += 512 * 16) g_labels[i] = l32[i];
    }
}

__global__ __launch_bounds__(NTHREADS) void row_kernel(const float* __restrict__ sim) {
    const int row  = blockIdx.x;
    const int tid  = threadIdx.x;
    const int lane = tid & 31;
    const int warp = tid >> 5;
    const int my_label = g_labels[row];

    const float4* __restrict__ srow4 = reinterpret_cast<const float4*>(sim + (size_t)row * BN);
    const int4*   __restrict__ lab4  = reinterpret_cast<const int4*>(g_labels);

    float v[PER];
    float mn = CUDART_INF_F;    // min over positives (original s)
    float mx = -CUDART_INF_F;   // max over x (== max over negatives, poison can't win)

    #pragma unroll
    for (int k = 0; k < PER / 4; k++) {
        int j4 = tid + k * NTHREADS;               // coalesced float4 index
        float4 s4 = srow4[j4];
        int4   l4 = lab4[j4];
        float sv[4] = {s4.x, s4.y, s4.z, s4.w};
        int   lv[4] = {l4.x, l4.y, l4.z, l4.w};
        #pragma unroll
        for (int e = 0; e < 4; e++) {
            int idx = k * 4 + e;
            float s = sv[e];
            bool same = (lv[e] == my_label);
            bool pos  = same && (s < ONE_MEPS);
            if (pos) mn = fminf(mn, s);            // @p FMNMX
            float x = s;
            if (same) x -= POISON;                 // @p FADD (poison)
            v[idx] = x;
            mx = fmaxf(mx, x);                     // unpredicated FMNMX
        }
    }
    const float my_mn = mn;                        // thread-local pos trigger

    // ---- block reduce min_pos / max_neg ----
    __shared__ float s_mn[NWARPS], s_mx[NWARPS];
    __shared__ float s_minpos, s_maxneg;
    #pragma unroll
    for (int o = 16; o; o >>= 1) {
        mn = fminf(mn, __shfl_xor_sync(0xffffffffu, mn, o));
        mx = fmaxf(mx, __shfl_xor_sync(0xffffffffu, mx, o));
    }
    if (lane == 0) { s_mn[warp] = mn; s_mx[warp] = mx; }
    __syncthreads();
    if (warp == 0) {
        float a = (lane < NWARPS) ? s_mn[lane] : CUDART_INF_F;
        float b = (lane < NWARPS) ? s_mx[lane] : -CUDART_INF_F;
        #pragma unroll
        for (int o = 8; o; o >>= 1) {
            a = fminf(a, __shfl_xor_sync(0xffffffffu, a, o));
            b = fmaxf(b, __shfl_xor_sync(0xffffffffu, b, o));
        }
        if (lane == 0) { s_minpos = a; s_maxneg = b; }
    }
    __syncthreads();

    const float tn = s_minpos - 0.1f;   // neg kept iff x > tn (inf minpos -> none)

    // ---- dense neg pass: 4 issue slots / element ----
    float ns0 = 0.0f, ns1 = 0.0f;
    #pragma unroll
    for (int idx = 0; idx < PER; idx += 2) {
        float x0 = v[idx], x1 = v[idx + 1];
        float e0 = ex2(fmaf(x0, K40, C40));
        float e1 = ex2(fmaf(x1, K40, C40));
        if (x0 > tn) ns0 += e0;
        if (x1 > tn) ns1 += e1;
    }
    float neg_sum = ns0 + ns1;

    // ---- rare pos pass (thread has >=1 positive) ----
    float pos_sum = 0.0f;
    if (my_mn < CUDART_INF_F) {
        // pos element iff x <= PB; sel_pos additionally needs s - 0.1 < max_neg
        // i.e. x < max_neg - 3.9. Combine into one threshold (strict-< with the
        // float just above PB keeps x == PB included).
        float pb_up = __int_as_float(__float_as_int(PB) - 1);   // next float toward 0
        float tp = fminf(pb_up, s_maxneg - 3.9f);
        #pragma unroll
        for (int idx = 0; idx < PER; idx++) {
            float x = v[idx];
            float e = ex2(fmaf(x, KP, CP));
            if (x < tp) pos_sum += e;
        }
    }

    // ---- block reduce the two sums ----
    #pragma unroll
    for (int o = 16; o; o >>= 1) {
        pos_sum += __shfl_xor_sync(0xffffffffu, pos_sum, o);
        neg_sum += __shfl_xor_sync(0xffffffffu, neg_sum, o);
    }
    __shared__ float s_ps[NWARPS], s_ns[NWARPS];
    if (lane == 0) { s_ps[warp] = pos_sum; s_ns[warp] = neg_sum; }
    __syncthreads();
    if (tid == 0) {
        float ps = 0.0f, ns = 0.0f;
        #pragma unroll
        for (int w = 0; w < NWARPS; w++) { ps += s_ps[w]; ns += s_ns[w]; }
        // exp > 0 always, so ps>0 <=> any(sel_pos), ns>0 <=> any(sel_neg)
        float loss = 0.0f;
        if (ps > 0.0f && ns > 0.0f)
            loss = log1pf(ps) * 0.5f + log1pf(ns) * 0.025f;
        g_row_loss[row] = loss;
    }
}

__global__ __launch_bounds__(1024) void reduce_kernel(float* __restrict__ out) {
    int tid = threadIdx.x;
    float sum = 0.0f;
    #pragma unroll
    for (int i = 0; i < BN / 1024; i++) sum += g_row_loss[tid + i * 1024];
    __shared__ float s[32];
    #pragma unroll
    for (int o = 16; o; o >>= 1) sum += __shfl_xor_sync(0xffffffffu, sum, o);
    if ((tid & 31) == 0) s[tid >> 5] = sum;
    __syncthreads();
    if (tid < 32) {
        float x = s[tid];
        #pragma unroll
        for (int o = 16; o; o >>= 1) x += __shfl_xor_sync(0xffffffffu, x, o);
        if (tid == 0) out[0] = x / (float)BN;
    }
}

extern "C" void kernel_launch(void* const* d_in, const int* in_sizes, int n_in,
                              void* d_out, int out_size) {
    // Guard against input ordering: sim has BN*BN elements, labels BN.
    const void* p0 = d_in[0];
    const void* p1 = d_in[1];
    const float* sim;
    const void*  labels;
    if (in_sizes[0] == BN) { labels = p0; sim = (const float*)p1; }
    else                   { sim = (const float*)p0; labels = p1; }
    float* out = (float*)d_out;

    prep_labels_kernel<<<16, 512>>>(labels);
    row_kernel<<<BN, NTHREADS>>>(sim);
    reduce_kernel<<<1, 1024>>>(out);
}

// round 4
// speedup vs baseline: 1.6933x; 1.0167x over previous
#include <cuda_runtime.h>
#include <math_constants.h>

// MultiSimilarityLoss: sim_mat [8192,8192] f32, labels [8192] i64-or-i32 -> scalar f32
//
// Memory-roofline-oriented rewrite:
//  - All 8 LDG.128 (4 sim float4 + 4 label int4) front-batched -> MLP_p1=8.
//  - Poison encoding: same-labeled elements x = s - 4 (in [-5,-3]).
//    * min over ALL x == min over poisoned x (self always poisoned, negs >= -1),
//      so hardest-positive needs NO extra predicate: positives are x < PB.
//    * max over ALL x == max over negatives (poison can't win).
//    * pass1 = 4 insts/elem: ISETP, @FADD, FMNMX, FMNMX.
//  - Dense pass2 = FFMA + MUFU.EX2 + FSETP + @FADD, 4 accumulators.
//  - Pos-side exp in a rare branch (~39% of warps, ~1.5% of threads).

constexpr int BN        = 8192;
constexpr int NTHREADS  = 512;
constexpr int PER       = BN / NTHREADS;   // 16
constexpr int NWARPS    = NTHREADS / 32;   // 16

constexpr float ONE_MEPS = 1.0f - 1e-5f;          // pos threshold on s
constexpr float POISON   = 4.0f;
constexpr float PB       = ONE_MEPS - POISON;     // poisoned pos boundary ~ -3.00001
// exp(40(s-0.5)) = exp2(s*K40 + C40)
constexpr float K40 = 57.706801635558536f;        //  40*log2(e)
constexpr float C40 = -28.853400817779268f;       // -20*log2(e)
// exp(-2(s-0.5)) with s = x+4  ->  exp2(x*KP + CP)
constexpr float KP  = -2.885390081777927f;        //  -2*log2(e)
constexpr float CP  = -10.098865286222744f;       //  -7*log2(e)

__device__ int   g_labels[BN];
__device__ float g_row_loss[BN];

__device__ __forceinline__ float ex2(float a) {
    float r;
    asm("ex2.approx.ftz.f32 %0, %1;" : "=f"(r) : "f"(a));
    return r;
}

// Dtype detection: odd 32-bit words are high halves (all zero, labels<1024) iff
// int64. 32 sampled words: P(false positive for int32) = (1/1024)^32 ~ 0.
__global__ __launch_bounds__(512) void prep_labels_kernel(const void* __restrict__ labels_raw) {
    const int tid = threadIdx.x;
    const unsigned* w = (const unsigned*)labels_raw;

    __shared__ int s_is64;
    if (tid < 32) {
        unsigned f = w[2 * tid + 1];
        unsigned any = __ballot_sync(0xffffffffu, f != 0u);
        if (tid == 0) s_is64 = (any == 0u) ? 1 : 0;
    }
    __syncthreads();

    int start = blockIdx.x * 512 + tid;
    if (s_is64) {
        const long long* l64 = (const long long*)labels_raw;
        for (int i = start; i < BN; i += 512 * 16) g_labels[i] = (int)l64[i];
    } else {
        const int* l32 = (const int*)labels_raw;
        for (int i = start; i < BN; i += 512 * 16) g_labels[i] = l32[i];
    }
}

__global__ __launch_bounds__(NTHREADS) void row_kernel(const float* __restrict__ sim) {
    const int row  = blockIdx.x;
    const int tid  = threadIdx.x;
    const int lane = tid & 31;
    const int warp = tid >> 5;
    const int my_label = g_labels[row];

    const float4* __restrict__ srow4 = reinterpret_cast<const float4*>(sim + (size_t)row * BN);
    const int4*   __restrict__ lab4  = reinterpret_cast<const int4*>(g_labels);

    // ---- front-batched loads: 8 independent LDG.128 ----
    float4 s4[PER / 4];
    int4   l4[PER / 4];
    #pragma unroll
    for (int k = 0; k < PER / 4; k++) s4[k] = srow4[tid + k * NTHREADS];
    #pragma unroll
    for (int k = 0; k < PER / 4; k++) l4[k] = lab4[tid + k * NTHREADS];

    // ---- pass 1: poison + min/max over x (4 insts/elem) ----
    float v[PER];
    float mn = CUDART_INF_F;    // min over all x == min over poisoned x
    float mx = -CUDART_INF_F;   // max over all x == max over negatives

    #pragma unroll
    for (int k = 0; k < PER / 4; k++) {
        float sv[4] = {s4[k].x, s4[k].y, s4[k].z, s4[k].w};
        int   lv[4] = {l4[k].x, l4[k].y, l4[k].z, l4[k].w};
        #pragma unroll
        for (int e = 0; e < 4; e++) {
            float x = sv[e];
            if (lv[e] == my_label) x -= POISON;    // ISETP + @FADD
            v[k * 4 + e] = x;
            mn = fminf(mn, x);                     // FMNMX
            mx = fmaxf(mx, x);                     // FMNMX
        }
    }
    const float my_mn = mn;                        // thread-local pos trigger

    // ---- block reduce min_all / max_neg ----
    __shared__ float s_mn[NWARPS], s_mx[NWARPS];
    __shared__ float s_minall, s_maxneg;
    #pragma unroll
    for (int o = 16; o; o >>= 1) {
        mn = fminf(mn, __shfl_xor_sync(0xffffffffu, mn, o));
        mx = fmaxf(mx, __shfl_xor_sync(0xffffffffu, mx, o));
    }
    if (lane == 0) { s_mn[warp] = mn; s_mx[warp] = mx; }
    __syncthreads();
    if (warp == 0) {
        float a = (lane < NWARPS) ? s_mn[lane] : CUDART_INF_F;
        float b = (lane < NWARPS) ? s_mx[lane] : -CUDART_INF_F;
        #pragma unroll
        for (int o = 8; o; o >>= 1) {
            a = fminf(a, __shfl_xor_sync(0xffffffffu, a, o));
            b = fmaxf(b, __shfl_xor_sync(0xffffffffu, b, o));
        }
        if (lane == 0) { s_minall = a; s_maxneg = b; }
    }
    __syncthreads();

    const float pb_up = __int_as_float(__float_as_int(PB) - 1);  // next float toward 0
    // Positive exists iff min_all <= PB (i.e. < pb_up). Then hardest positive
    // (poisoned) = min_all, and sel_neg threshold tn = min_pos - 0.1 = min_all + 3.9.
    const float min_all = s_minall;
    const float tn = (min_all < pb_up) ? (min_all + 3.9f) : CUDART_INF_F;

    // ---- dense neg pass: FFMA + MUFU + FSETP + @FADD, 4 accumulators ----
    float ns0 = 0.0f, ns1 = 0.0f, ns2 = 0.0f, ns3 = 0.0f;
    #pragma unroll
    for (int idx = 0; idx < PER; idx += 4) {
        float x0 = v[idx], x1 = v[idx + 1], x2 = v[idx + 2], x3 = v[idx + 3];
        float e0 = ex2(fmaf(x0, K40, C40));
        float e1 = ex2(fmaf(x1, K40, C40));
        float e2 = ex2(fmaf(x2, K40, C40));
        float e3 = ex2(fmaf(x3, K40, C40));
        if (x0 > tn) ns0 += e0;    // poisoned x <= -3 < tn always (tn >= -1.1)
        if (x1 > tn) ns1 += e1;
        if (x2 > tn) ns2 += e2;
        if (x3 > tn) ns3 += e3;
    }
    float neg_sum = (ns0 + ns1) + (ns2 + ns3);

    // ---- rare pos pass (this thread owns >= 1 positive) ----
    float pos_sum = 0.0f;
    if (my_mn < pb_up) {
        // sel_pos: x <= PB (positive) AND s - 0.1 < max_neg i.e. x < max_neg - 3.9
        float tp = fminf(pb_up, s_maxneg - 3.9f);
        #pragma unroll
        for (int idx = 0; idx < PER; idx++) {
            float x = v[idx];
            float e = ex2(fmaf(x, KP, CP));   // exp(-2(s-0.5)) on poisoned x
            if (x < tp) pos_sum += e;
        }
    }

    // ---- block reduce the two sums ----
    #pragma unroll
    for (int o = 16; o; o >>= 1) {
        pos_sum += __shfl_xor_sync(0xffffffffu, pos_sum, o);
        neg_sum += __shfl_xor_sync(0xffffffffu, neg_sum, o);
    }
    __shared__ float s_ps[NWARPS], s_ns[NWARPS];
    if (lane == 0) { s_ps[warp] = pos_sum; s_ns[warp] = neg_sum; }
    __syncthreads();
    if (tid == 0) {
        float ps = 0.0f, ns = 0.0f;
        #pragma unroll
        for (int w = 0; w < NWARPS; w++) { ps += s_ps[w]; ns += s_ns[w]; }
        // exp > 0 always, so ps>0 <=> any(sel_pos), ns>0 <=> any(sel_neg)
        float loss = 0.0f;
        if (ps > 0.0f && ns > 0.0f)
            loss = log1pf(ps) * 0.5f + log1pf(ns) * 0.025f;
        g_row_loss[row] = loss;
    }
}

__global__ __launch_bounds__(1024) void reduce_kernel(float* __restrict__ out) {
    int tid = threadIdx.x;
    float sum = 0.0f;
    #pragma unroll
    for (int i = 0; i < BN / 1024; i++) sum += g_row_loss[tid + i * 1024];
    __shared__ float s[32];
    #pragma unroll
    for (int o = 16; o; o >>= 1) sum += __shfl_xor_sync(0xffffffffu, sum, o);
    if ((tid & 31) == 0) s[tid >> 5] = sum;
    __syncthreads();
    if (tid < 32) {
        float x = s[tid];
        #pragma unroll
        for (int o = 16; o; o >>= 1) x += __shfl_xor_sync(0xffffffffu, x, o);
        if (tid == 0) out[0] = x / (float)BN;
    }
}

extern "C" void kernel_launch(void* const* d_in, const int* in_sizes, int n_in,
                              void* d_out, int out_size) {
    // Guard against input ordering: sim has BN*BN elements, labels BN.
    const void* p0 = d_in[0];
    const void* p1 = d_in[1];
    const float* sim;
    const void*  labels;
    if (in_sizes[0] == BN) { labels = p0; sim = (const float*)p1; }
    else                   { sim = (const float*)p0; labels = p1; }
    float* out = (float*)d_out;

    prep_labels_kernel<<<16, 512>>>(labels);
    row_kernel<<<BN, NTHREADS>>>(sim);
    reduce_kernel<<<1, 1024>>>(out);
}

// round 5
// speedup vs baseline: 1.7346x; 1.0244x over previous
#include <cuda_runtime.h>
#include <math_constants.h>

// MultiSimilarityLoss: sim_mat [8192,8192] f32, labels [8192] i64-or-i32 -> scalar f32
//
// R5: cache-policy split. sim is streamed ONCE -> ld.global.cs (evict-first),
// so the 32 KB g_labels array stays L1-resident across the ~55 CTAs/SM,
// eliminating ~256 MB of label L2 traffic (the R4 post-mortem's binding term).
//
//  - Poison encoding: same-labeled elements x = s - 4 (in [-5,-3]).
//    * min over ALL x == hardest positive (self always poisoned, negs >= -1).
//    * max over ALL x == hardest negative (poison can't win).
//  - Dense pass2 = FFMA + MUFU.EX2 + FSETP + @FADD, 4 accumulators.
//  - Pos-side exp in a rare branch (~39% of warps, ~1.5% of threads).

constexpr int BN        = 8192;
constexpr int NTHREADS  = 512;
constexpr int PER       = BN / NTHREADS;   // 16
constexpr int NWARPS    = NTHREADS / 32;   // 16

constexpr float ONE_MEPS = 1.0f - 1e-5f;          // pos threshold on s
constexpr float POISON   = 4.0f;
constexpr float PB       = ONE_MEPS - POISON;     // poisoned pos boundary ~ -3.00001
// exp(40(s-0.5)) = exp2(s*K40 + C40)
constexpr float K40 = 57.706801635558536f;        //  40*log2(e)
constexpr float C40 = -28.853400817779268f;       // -20*log2(e)
// exp(-2(s-0.5)) with s = x+4  ->  exp2(x*KP + CP)
constexpr float KP  = -2.885390081777927f;        //  -2*log2(e)
constexpr float CP  = -10.098865286222744f;       //  -7*log2(e)

__device__ int   g_labels[BN];
__device__ float g_row_loss[BN];

__device__ __forceinline__ float ex2(float a) {
    float r;
    asm("ex2.approx.ftz.f32 %0, %1;" : "=f"(r) : "f"(a));
    return r;
}

// Streaming (evict-first) 128-bit load: touched exactly once, don't pollute L1.
__device__ __forceinline__ float4 ldcs4(const float4* p) {
    float4 r;
    asm("ld.global.cs.v4.f32 {%0,%1,%2,%3}, [%4];"
        : "=f"(r.x), "=f"(r.y), "=f"(r.z), "=f"(r.w) : "l"(p));
    return r;
}

// Dtype detection: odd 32-bit words are high halves (all zero, labels<1024) iff
// int64. 32 sampled words: P(false positive for int32) = (1/1024)^32 ~ 0.
__global__ __launch_bounds__(512) void prep_labels_kernel(const void* __restrict__ labels_raw) {
    const int tid = threadIdx.x;
    const unsigned* w = (const unsigned*)labels_raw;

    __shared__ int s_is64;
    if (tid < 32) {
        unsigned f = w[2 * tid + 1];
        unsigned any = __ballot_sync(0xffffffffu, f != 0u);
        if (tid == 0) s_is64 = (any == 0u) ? 1 : 0;
    }
    __syncthreads();

    int start = blockIdx.x * 512 + tid;
    if (s_is64) {
        const long long* l64 = (const long long*)labels_raw;
        for (int i = start; i < BN; i += 512 * 16) g_labels[i] = (int)l64[i];
    } else {
        const int* l32 = (const int*)labels_raw;
        for (int i = start; i < BN; i += 512 * 16) g_labels[i] = l32[i];
    }
}

__global__ __launch_bounds__(NTHREADS) void row_kernel(const float* __restrict__ sim) {
    const int row  = blockIdx.x;
    const int tid  = threadIdx.x;
    const int lane = tid & 31;
    const int warp = tid >> 5;
    const int my_label = __ldg(&g_labels[row]);

    const float4* __restrict__ srow4 = reinterpret_cast<const float4*>(sim + (size_t)row * BN);
    const int4*   __restrict__ lab4  = reinterpret_cast<const int4*>(g_labels);

    // ---- front-batched loads: sim streamed (evict-first), labels L1-cached ----
    float4 s4[PER / 4];
    int4   l4[PER / 4];
    #pragma unroll
    for (int k = 0; k < PER / 4; k++) s4[k] = ldcs4(srow4 + tid + k * NTHREADS);
    #pragma unroll
    for (int k = 0; k < PER / 4; k++) l4[k] = __ldg(lab4 + tid + k * NTHREADS);

    // ---- pass 1: poison + min/max over x (4 insts/elem) ----
    float v[PER];
    float mn = CUDART_INF_F;    // min over all x == min over poisoned x
    float mx = -CUDART_INF_F;   // max over all x == max over negatives

    #pragma unroll
    for (int k = 0; k < PER / 4; k++) {
        float sv[4] = {s4[k].x, s4[k].y, s4[k].z, s4[k].w};
        int   lv[4] = {l4[k].x, l4[k].y, l4[k].z, l4[k].w};
        #pragma unroll
        for (int e = 0; e < 4; e++) {
            float x = sv[e];
            if (lv[e] == my_label) x -= POISON;    // ISETP + @FADD
            v[k * 4 + e] = x;
            mn = fminf(mn, x);                     // FMNMX
            mx = fmaxf(mx, x);                     // FMNMX
        }
    }
    const float my_mn = mn;                        // thread-local pos trigger

    // ---- block reduce min_all / max_neg ----
    __shared__ float s_mn[NWARPS], s_mx[NWARPS];
    __shared__ float s_minall, s_maxneg;
    #pragma unroll
    for (int o = 16; o; o >>= 1) {
        mn = fminf(mn, __shfl_xor_sync(0xffffffffu, mn, o));
        mx = fmaxf(mx, __shfl_xor_sync(0xffffffffu, mx, o));
    }
    if (lane == 0) { s_mn[warp] = mn; s_mx[warp] = mx; }
    __syncthreads();
    if (warp == 0) {
        float a = (lane < NWARPS) ? s_mn[lane] : CUDART_INF_F;
        float b = (lane < NWARPS) ? s_mx[lane] : -CUDART_INF_F;
        #pragma unroll
        for (int o = 8; o; o >>= 1) {
            a = fminf(a, __shfl_xor_sync(0xffffffffu, a, o));
            b = fmaxf(b, __shfl_xor_sync(0xffffffffu, b, o));
        }
        if (lane == 0) { s_minall = a; s_maxneg = b; }
    }
    __syncthreads();

    const float pb_up = __int_as_float(__float_as_int(PB) - 1);  // next float toward 0
    // Positive exists iff min_all <= PB (i.e. < pb_up). Then hardest positive
    // (poisoned) = min_all, and sel_neg threshold tn = min_pos - 0.1 = min_all + 3.9.
    const float min_all = s_minall;
    const float tn = (min_all < pb_up) ? (min_all + 3.9f) : CUDART_INF_F;

    // ---- dense neg pass: FFMA + MUFU + FSETP + @FADD, 4 accumulators ----
    float ns0 = 0.0f, ns1 = 0.0f, ns2 = 0.0f, ns3 = 0.0f;
    #pragma unroll
    for (int idx = 0; idx < PER; idx += 4) {
        float x0 = v[idx], x1 = v[idx + 1], x2 = v[idx + 2], x3 = v[idx + 3];
        float e0 = ex2(fmaf(x0, K40, C40));
        float e1 = ex2(fmaf(x1, K40, C40));
        float e2 = ex2(fmaf(x2, K40, C40));
        float e3 = ex2(fmaf(x3, K40, C40));
        if (x0 > tn) ns0 += e0;    // poisoned x <= -3 < tn always (tn >= -1.1)
        if (x1 > tn) ns1 += e1;
        if (x2 > tn) ns2 += e2;
        if (x3 > tn) ns3 += e3;
    }
    float neg_sum = (ns0 + ns1) + (ns2 + ns3);

    // ---- rare pos pass (this thread owns >= 1 positive) ----
    float pos_sum = 0.0f;
    if (my_mn < pb_up) {
        // sel_pos: x <= PB (positive) AND s - 0.1 < max_neg i.e. x < max_neg - 3.9
        float tp = fminf(pb_up, s_maxneg - 3.9f);
        #pragma unroll
        for (int idx = 0; idx < PER; idx++) {
            float x = v[idx];
            float e = ex2(fmaf(x, KP, CP));   // exp(-2(s-0.5)) on poisoned x
            if (x < tp) pos_sum += e;
        }
    }

    // ---- block reduce the two sums ----
    #pragma unroll
    for (int o = 16; o; o >>= 1) {
        pos_sum += __shfl_xor_sync(0xffffffffu, pos_sum, o);
        neg_sum += __shfl_xor_sync(0xffffffffu, neg_sum, o);
    }
    __shared__ float s_ps[NWARPS], s_ns[NWARPS];
    if (lane == 0) { s_ps[warp] = pos_sum; s_ns[warp] = neg_sum; }
    __syncthreads();
    if (tid == 0) {
        float ps = 0.0f, ns = 0.0f;
        #pragma unroll
        for (int w = 0; w < NWARPS; w++) { ps += s_ps[w]; ns += s_ns[w]; }
        // exp > 0 always, so ps>0 <=> any(sel_pos), ns>0 <=> any(sel_neg)
        float loss = 0.0f;
        if (ps > 0.0f && ns > 0.0f)
            loss = log1pf(ps) * 0.5f + log1pf(ns) * 0.025f;
        g_row_loss[row] = loss;
    }
}

__global__ __launch_bounds__(1024) void reduce_kernel(float* __restrict__ out) {
    int tid = threadIdx.x;
    float sum = 0.0f;
    #pragma unroll
    for (int i = 0; i < BN / 1024; i++) sum += g_row_loss[tid + i * 1024];
    __shared__ float s[32];
    #pragma unroll
    for (int o = 16; o; o >>= 1) sum += __shfl_xor_sync(0xffffffffu, sum, o);
    if ((tid & 31) == 0) s[tid >> 5] = sum;
    __syncthreads();
    if (tid < 32) {
        float x = s[tid];
        #pragma unroll
        for (int o = 16; o; o >>= 1) x += __shfl_xor_sync(0xffffffffu, x, o);
        if (tid == 0) out[0] = x / (float)BN;
    }
}

extern "C" void kernel_launch(void* const* d_in, const int* in_sizes, int n_in,
                              void* d_out, int out_size) {
    // Guard against input ordering: sim has BN*BN elements, labels BN.
    const void* p0 = d_in[0];
    const void* p1 = d_in[1];
    const float* sim;
    const void*  labels;
    if (in_sizes[0] == BN) { labels = p0; sim = (const float*)p1; }
    else                   { sim = (const float*)p0; labels = p1; }
    float* out = (float*)d_out;

    prep_labels_kernel<<<16, 512>>>(labels);
    row_kernel<<<BN, NTHREADS>>>(sim);
    reduce_kernel<<<1, 1024>>>(out);
}

// round 6
// speedup vs baseline: 1.9811x; 1.1421x over previous
#include <cuda_runtime.h>
#include <math_constants.h>

// MultiSimilarityLoss: sim_mat [8192,8192] f32, labels [8192] i64-or-i32 -> scalar f32
//
// R6: occupancy rebuild. Per-element poisoned values live in a 32 KB smem
// buffer instead of 16 registers/thread. 256 threads x 32 elems/thread,
// __launch_bounds__(256,5): ~48 regs -> 5 CTAs / 40 warps per SM, so load
// issue from other CTAs covers each CTA's barrier/reduce/exp phases.
//
//  - Poison: same-labeled elements x = s - 4 (in [-5,-3]).
//    * min over ALL x == hardest positive (self always poisoned, negs >= -1).
//    * max over ALL x == hardest negative (poison can't win).
//  - Dense pass2: LDS.128 + 4x(FFMA + MUFU.EX2 + FSETP + @FADD).
//  - Pos-side exp in a rare branch (~1.5% of threads).

constexpr int BN        = 8192;
constexpr int NTHREADS  = 256;
constexpr int PER       = BN / NTHREADS;   // 32
constexpr int NVEC      = PER / 4;         // 8 float4 slots per thread
constexpr int NWARPS    = NTHREADS / 32;   // 8

constexpr float ONE_MEPS = 1.0f - 1e-5f;          // pos threshold on s
constexpr float POISON   = 4.0f;
constexpr float PB       = ONE_MEPS - POISON;     // poisoned pos boundary ~ -3.00001
// exp(40(s-0.5)) = exp2(x*K40 + C40)
constexpr float K40 = 57.706801635558536f;        //  40*log2(e)
constexpr float C40 = -28.853400817779268f;       // -20*log2(e)
// exp(-2(s-0.5)) with s = x+4  ->  exp2(x*KP + CP)
constexpr float KP  = -2.885390081777927f;        //  -2*log2(e)
constexpr float CP  = -10.098865286222744f;       //  -7*log2(e)

__device__ int   g_labels[BN];
__device__ float g_row_loss[BN];

__device__ __forceinline__ float ex2(float a) {
    float r;
    asm("ex2.approx.ftz.f32 %0, %1;" : "=f"(r) : "f"(a));
    return r;
}

// Streaming (evict-first) 128-bit load: touched exactly once.
__device__ __forceinline__ float4 ldcs4(const float4* p) {
    float4 r;
    asm("ld.global.cs.v4.f32 {%0,%1,%2,%3}, [%4];"
        : "=f"(r.x), "=f"(r.y), "=f"(r.z), "=f"(r.w) : "l"(p));
    return r;
}

// Dtype detection: odd 32-bit words are high halves (all zero, labels<1024) iff
// int64. 32 sampled words: P(false positive for int32) = (1/1024)^32 ~ 0.
__global__ __launch_bounds__(512) void prep_labels_kernel(const void* __restrict__ labels_raw) {
    const int tid = threadIdx.x;
    const unsigned* w = (const unsigned*)labels_raw;

    __shared__ int s_is64;
    if (tid < 32) {
        unsigned f = w[2 * tid + 1];
        unsigned any = __ballot_sync(0xffffffffu, f != 0u);
        if (tid == 0) s_is64 = (any == 0u) ? 1 : 0;
    }
    __syncthreads();

    int start = blockIdx.x * 512 + tid;
    if (s_is64) {
        const long long* l64 = (const long long*)labels_raw;
        for (int i = start; i < BN; i += 512 * 16) g_labels[i] = (int)l64[i];
    } else {
        const int* l32 = (const int*)labels_raw;
        for (int i = start; i < BN; i += 512 * 16) g_labels[i] = l32[i];
    }
}

__global__ __launch_bounds__(NTHREADS, 5) void row_kernel(const float* __restrict__ sim) {
    const int row  = blockIdx.x;
    const int tid  = threadIdx.x;
    const int lane = tid & 31;
    const int warp = tid >> 5;
    const int my_label = __ldg(&g_labels[row]);

    // 32 KB poisoned-value buffer: slot j4 (0..7) x thread -> conflict-free LDS.128.
    __shared__ float4 vsm[NVEC * NTHREADS];
    __shared__ float s_mn[NWARPS], s_mx[NWARPS];
    __shared__ float s_minall, s_maxneg;
    __shared__ float s_ps[NWARPS], s_ns[NWARPS];

    const float4* __restrict__ srow4 = reinterpret_cast<const float4*>(sim + (size_t)row * BN);
    const int4*   __restrict__ lab4  = reinterpret_cast<const int4*>(g_labels);

    // ---- pass 1: two chunks of (4 sim float4 + 4 label int4) front-batched ----
    float mn = CUDART_INF_F;    // min over all x == hardest positive (poisoned)
    float mx = -CUDART_INF_F;   // max over all x == hardest negative

    #pragma unroll
    for (int c = 0; c < 2; c++) {
        float4 a[4];
        int4   b[4];
        #pragma unroll
        for (int k = 0; k < 4; k++) a[k] = ldcs4(srow4 + tid + (c * 4 + k) * NTHREADS);
        #pragma unroll
        for (int k = 0; k < 4; k++) b[k] = __ldg(lab4 + tid + (c * 4 + k) * NTHREADS);
        #pragma unroll
        for (int k = 0; k < 4; k++) {
            float sv[4] = {a[k].x, a[k].y, a[k].z, a[k].w};
            int   lv[4] = {b[k].x, b[k].y, b[k].z, b[k].w};
            float xv[4];
            #pragma unroll
            for (int e = 0; e < 4; e++) {
                float x = sv[e];
                if (lv[e] == my_label) x -= POISON;    // ISETP + @FADD
                xv[e] = x;
                mn = fminf(mn, x);                     // FMNMX
                mx = fmaxf(mx, x);                     // FMNMX
            }
            vsm[(c * 4 + k) * NTHREADS + tid] = make_float4(xv[0], xv[1], xv[2], xv[3]);
        }
    }
    const float my_mn = mn;                            // thread-local pos trigger

    // ---- block reduce min_all / max_neg ----
    #pragma unroll
    for (int o = 16; o; o >>= 1) {
        mn = fminf(mn, __shfl_xor_sync(0xffffffffu, mn, o));
        mx = fmaxf(mx, __shfl_xor_sync(0xffffffffu, mx, o));
    }
    if (lane == 0) { s_mn[warp] = mn; s_mx[warp] = mx; }
    __syncthreads();
    if (warp == 0) {
        float a = (lane < NWARPS) ? s_mn[lane] : CUDART_INF_F;
        float b = (lane < NWARPS) ? s_mx[lane] : -CUDART_INF_F;
        #pragma unroll
        for (int o = 4; o; o >>= 1) {
            a = fminf(a, __shfl_xor_sync(0xffffffffu, a, o));
            b = fmaxf(b, __shfl_xor_sync(0xffffffffu, b, o));
        }
        if (lane == 0) { s_minall = a; s_maxneg = b; }
    }
    __syncthreads();

    const float pb_up = __int_as_float(__float_as_int(PB) - 1);  // next float toward 0
    // Positive exists iff min_all < pb_up. Then hardest positive (poisoned) =
    // min_all, and sel_neg threshold tn = min_pos - 0.1 = min_all + 3.9.
    const float min_all = s_minall;
    const float tn = (min_all < pb_up) ? (min_all + 3.9f) : CUDART_INF_F;

    // ---- dense neg pass from smem: LDS.128 + 4x(FFMA+MUFU+FSETP+@FADD) ----
    float ns0 = 0.0f, ns1 = 0.0f, ns2 = 0.0f, ns3 = 0.0f;
    #pragma unroll
    for (int j = 0; j < NVEC; j++) {
        float4 x = vsm[j * NTHREADS + tid];
        float e0 = ex2(fmaf(x.x, K40, C40));
        float e1 = ex2(fmaf(x.y, K40, C40));
        float e2 = ex2(fmaf(x.z, K40, C40));
        float e3 = ex2(fmaf(x.w, K40, C40));
        if (x.x > tn) ns0 += e0;    // poisoned x <= -3 < tn always (tn >= -1.1)
        if (x.y > tn) ns1 += e1;
        if (x.z > tn) ns2 += e2;
        if (x.w > tn) ns3 += e3;
    }
    float neg_sum = (ns0 + ns1) + (ns2 + ns3);

    // ---- rare pos pass (this thread owns >= 1 positive) ----
    float pos_sum = 0.0f;
    if (my_mn < pb_up) {
        // sel_pos: x <= PB (positive) AND s - 0.1 < max_neg i.e. x < max_neg - 3.9
        float tp = fminf(pb_up, s_maxneg - 3.9f);
        #pragma unroll
        for (int j = 0; j < NVEC; j++) {
            float4 x = vsm[j * NTHREADS + tid];
            float e0 = ex2(fmaf(x.x, KP, CP));   // exp(-2(s-0.5)) on poisoned x
            float e1 = ex2(fmaf(x.y, KP, CP));
            float e2 = ex2(fmaf(x.z, KP, CP));
            float e3 = ex2(fmaf(x.w, KP, CP));
            if (x.x < tp) pos_sum += e0;
            if (x.y < tp) pos_sum += e1;
            if (x.z < tp) pos_sum += e2;
            if (x.w < tp) pos_sum += e3;
        }
    }

    // ---- block reduce the two sums ----
    #pragma unroll
    for (int o = 16; o; o >>= 1) {
        pos_sum += __shfl_xor_sync(0xffffffffu, pos_sum, o);
        neg_sum += __shfl_xor_sync(0xffffffffu, neg_sum, o);
    }
    if (lane == 0) { s_ps[warp] = pos_sum; s_ns[warp] = neg_sum; }
    __syncthreads();
    if (tid == 0) {
        float ps = 0.0f, ns = 0.0f;
        #pragma unroll
        for (int w = 0; w < NWARPS; w++) { ps += s_ps[w]; ns += s_ns[w]; }
        // exp > 0 always, so ps>0 <=> any(sel_pos), ns>0 <=> any(sel_neg)
        float loss = 0.0f;
        if (ps > 0.0f && ns > 0.0f)
            loss = log1pf(ps) * 0.5f + log1pf(ns) * 0.025f;
        g_row_loss[row] = loss;
    }
}

__global__ __launch_bounds__(1024) void reduce_kernel(float* __restrict__ out) {
    int tid = threadIdx.x;
    float sum = 0.0f;
    #pragma unroll
    for (int i = 0; i < BN / 1024; i++) sum += g_row_loss[tid + i * 1024];
    __shared__ float s[32];
    #pragma unroll
    for (int o = 16; o; o >>= 1) sum += __shfl_xor_sync(0xffffffffu, sum, o);
    if ((tid & 31) == 0) s[tid >> 5] = sum;
    __syncthreads();
    if (tid < 32) {
        float x = s[tid];
        #pragma unroll
        for (int o = 16; o; o >>= 1) x += __shfl_xor_sync(0xffffffffu, x, o);
        if (tid == 0) out[0] = x / (float)BN;
    }
}

extern "C" void kernel_launch(void* const* d_in, const int* in_sizes, int n_in,
                              void* d_out, int out_size) {
    // Guard against input ordering: sim has BN*BN elements, labels BN.
    const void* p0 = d_in[0];
    const void* p1 = d_in[1];
    const float* sim;
    const void*  labels;
    if (in_sizes[0] == BN) { labels = p0; sim = (const float*)p1; }
    else                   { sim = (const float*)p0; labels = p1; }
    float* out = (float*)d_out;

    prep_labels_kernel<<<16, 512>>>(labels);
    row_kernel<<<BN, NTHREADS>>>(sim);
    reduce_kernel<<<1, 1024>>>(out);
}